// round 12
// baseline (speedup 1.0000x reference)
#include <cuda_runtime.h>
#include <cuda_bf16.h>
#include <math.h>

#define VOCAB 32000
#define H 512
#define B 10
#define KB 431
#define KB_PAD 1523
#define KBW (KB_PAD + KB)      // 1954
#define L H                     // 512

// d_out layout (floats), concatenation of the 5 reference outputs:
#define OUT_OFF   0
#define CTX_OFF   (VOCAB * B)                 // 320000
#define HID_OFF   (CTX_OFF + B * H)           // 325120
#define ATTN_OFF  (HID_OFF + B * H)           // 330240
#define KBA_OFF   (ATTN_OFF + B * L)          // 335360
#define KBA_TOT   (B * L * KBW)               // 10004480
#define N4        (KBA_TOT / 4)               // 2501120

// scratch (no device allocation allowed)
__device__ float g_h1[B * H];
__device__ float g_concat[B * H];

__device__ __forceinline__ float dot4(float4 a, float4 b) {
    return a.x * b.x + a.y * b.y + a.z * b.z + a.w * b.w;
}

__device__ __forceinline__ float warp_sum(float v) {
#pragma unroll
    for (int o = 16; o > 0; o >>= 1) v += __shfl_xor_sync(0xFFFFFFFFu, v, o);
    return v;
}

__device__ __forceinline__ float sigmoidf_(float x) {
    return 1.0f / (1.0f + __expf(-x));
}

// ---------------------------------------------------------------------------
// kb kernel (side stream): grid-stride over output float4 quads.
// Fast path: quad inside one (b,p) row; slow path handles row straddle.
// ---------------------------------------------------------------------------
__global__ void __launch_bounds__(256)
kb_kernel(const int* __restrict__ kb_inputs,
          const float* __restrict__ emb_kb,
          float* __restrict__ d_out) {
    const unsigned ROW = (unsigned)L * KBW;   // 1000448
    unsigned stride = gridDim.x * blockDim.x;
    for (unsigned i4 = blockIdx.x * blockDim.x + threadIdx.x; i4 < (unsigned)N4;
         i4 += stride) {
        unsigned t   = i4 * 4u;
        unsigned b   = t / ROW;
        unsigned rem = t - b * ROW;
        unsigned p   = rem / KBW;
        unsigned c   = rem - p * KBW;
        float v[4] = {0.f, 0.f, 0.f, 0.f};

        if (c + 3u < (unsigned)KBW) {
            if (c + 3u >= (unsigned)KB_PAD) {
#pragma unroll
                for (int j = 0; j < 4; j++) {
                    unsigned cj = c + j;
                    if (cj >= (unsigned)KB_PAD) {
                        unsigned f = p * KB + (cj - KB_PAD);
                        unsigned kbr = f >> 9, h = f & 511u;
                        const int* idx = kb_inputs + ((long)b * KB + kbr) * 3;
                        v[j] = __ldg(&emb_kb[(long)__ldg(idx + 0) * H + h])
                             + __ldg(&emb_kb[(long)__ldg(idx + 1) * H + h])
                             + __ldg(&emb_kb[(long)__ldg(idx + 2) * H + h]);
                    }
                }
            }
        } else {
#pragma unroll
            for (int j = 0; j < 4; j++) {
                unsigned tj = t + j;
                unsigned bj = tj / ROW;
                unsigned rj = tj - bj * ROW;
                unsigned pj = rj / KBW;
                unsigned cj = rj - pj * KBW;
                if (cj >= (unsigned)KB_PAD) {
                    unsigned f = pj * KB + (cj - KB_PAD);
                    unsigned kbr = f >> 9, h = f & 511u;
                    const int* idx = kb_inputs + ((long)bj * KB + kbr) * 3;
                    v[j] = __ldg(&emb_kb[(long)__ldg(idx + 0) * H + h])
                         + __ldg(&emb_kb[(long)__ldg(idx + 1) * H + h])
                         + __ldg(&emb_kb[(long)__ldg(idx + 2) * H + h]);
                }
            }
        }
        float4 o;
        o.x = v[0]; o.y = v[1]; o.z = v[2]; o.w = v[3];
        ((float4*)(d_out + KBA_OFF))[i4] = o;
    }
}

// ---------------------------------------------------------------------------
// Kernel 1: GRU step. grid = H blocks, 320 threads (warp = batch b).
// Also writes hidden output and zeros context slab.
// ---------------------------------------------------------------------------
__global__ void __launch_bounds__(320)
gru_kernel(const int* __restrict__ seq,
           const float* __restrict__ emb,
           const float* __restrict__ h0,
           const float* __restrict__ w_ih,
           const float* __restrict__ w_hh,
           const float* __restrict__ b_ih,
           const float* __restrict__ b_hh,
           float* __restrict__ d_out) {
    int j = blockIdx.x;
    int b = threadIdx.x >> 5;
    int lane = threadIdx.x & 31;
    if (b >= B) return;

    const float4* x4  = (const float4*)(emb + (long)seq[b] * H);
    const float4* h4  = (const float4*)(h0 + b * H);
    const float4* wir = (const float4*)(w_ih + (long)j * H);
    const float4* wiz = (const float4*)(w_ih + (long)(H + j) * H);
    const float4* win = (const float4*)(w_ih + (long)(2 * H + j) * H);
    const float4* whr = (const float4*)(w_hh + (long)j * H);
    const float4* whz = (const float4*)(w_hh + (long)(H + j) * H);
    const float4* whn = (const float4*)(w_hh + (long)(2 * H + j) * H);

    float sir = 0.f, siz = 0.f, sin_ = 0.f, shr = 0.f, shz = 0.f, shn = 0.f;
#pragma unroll
    for (int c = lane; c < H / 4; c += 32) {
        float4 xv = x4[c], hv = h4[c];
        sir  += dot4(xv, wir[c]);
        siz  += dot4(xv, wiz[c]);
        sin_ += dot4(xv, win[c]);
        shr  += dot4(hv, whr[c]);
        shz  += dot4(hv, whz[c]);
        shn  += dot4(hv, whn[c]);
    }
    sir = warp_sum(sir);  siz = warp_sum(siz);  sin_ = warp_sum(sin_);
    shr = warp_sum(shr);  shz = warp_sum(shz);  shn  = warp_sum(shn);

    if (lane == 0) {
        float gir = sir + b_ih[j];
        float giz = siz + b_ih[H + j];
        float gin = sin_ + b_ih[2 * H + j];
        float ghr = shr + b_hh[j];
        float ghz = shz + b_hh[H + j];
        float ghn = shn + b_hh[2 * H + j];
        float r = sigmoidf_(gir + ghr);
        float z = sigmoidf_(giz + ghz);
        float n = tanhf(gin + r * ghn);
        float hprev = h0[b * H + j];
        float h1 = (1.0f - z) * n + z * hprev;
        g_h1[b * H + j] = h1;
        d_out[HID_OFF + b * H + j] = h1;
        d_out[CTX_OFF + b * H + j] = 0.0f;  // zero context for atomicAdd
    }
}

// ---------------------------------------------------------------------------
// Kernel 2: energies + softmax over batch (axis 0). grid = L blocks, 320 thr.
// ---------------------------------------------------------------------------
__global__ void __launch_bounds__(320)
attn_kernel(const float* __restrict__ enc,
            float* __restrict__ d_out) {
    int l = blockIdx.x;
    int b = threadIdx.x >> 5;
    int lane = threadIdx.x & 31;
    __shared__ float e_s[B];

    if (b < B) {
        const float4* h4 = (const float4*)(g_h1 + b * H);
        const float4* e4 = (const float4*)(enc + ((long)l * B + b) * H);
        float s = 0.f;
#pragma unroll
        for (int c = lane; c < H / 4; c += 32) s += dot4(h4[c], e4[c]);
        s = warp_sum(s);
        if (lane == 0) e_s[b] = s;
    }
    __syncthreads();
    if (threadIdx.x < B) {
        float m = -1e30f;
#pragma unroll
        for (int i = 0; i < B; i++) m = fmaxf(m, e_s[i]);
        float sum = 0.f;
#pragma unroll
        for (int i = 0; i < B; i++) sum += __expf(e_s[i] - m);
        float a = __expf(e_s[threadIdx.x] - m) / sum;
        d_out[ATTN_OFF + threadIdx.x * L + l] = a;
    }
}

// ---------------------------------------------------------------------------
// Kernel 3: context[b,h] = sum_l a[b,l]*enc[l,b,h]. 160 blocks (b, l-chunk
// of 32) x 512 thr. Explicit 8-wide load batches force front-batched LDGs.
// ---------------------------------------------------------------------------
__global__ void __launch_bounds__(512)
ctx_kernel(const float* __restrict__ enc,
           float* __restrict__ d_out) {
    __shared__ float a_s[32];
    int b  = blockIdx.x >> 4;
    int lc = blockIdx.x & 15;
    int h  = threadIdx.x;

    if (threadIdx.x < 32)
        a_s[threadIdx.x] = d_out[ATTN_OFF + b * L + lc * 32 + threadIdx.x];
    __syncthreads();

    const float* ep = enc + ((long)(lc * 32) * B + b) * H + h;
    float acc = 0.f;
#pragma unroll
    for (int base = 0; base < 32; base += 8) {
        float r[8];
#pragma unroll
        for (int j = 0; j < 8; j++) r[j] = __ldg(ep + (long)(base + j) * B * H);
#pragma unroll
        for (int j = 0; j < 8; j++) acc = fmaf(a_s[base + j], r[j], acc);
    }
    atomicAdd(&d_out[CTX_OFF + b * H + h], acc);
}

// ---------------------------------------------------------------------------
// Kernel 4: concat_output = tanh([h1, ctx] @ w_concat.T + b_concat).
// grid = H blocks, warp per batch. All 16 load quads front-batched.
// ---------------------------------------------------------------------------
__global__ void __launch_bounds__(320)
concat_kernel(const float* __restrict__ w_concat,
              const float* __restrict__ b_concat,
              const float* __restrict__ d_out_ctx) {
    int j = blockIdx.x;
    int b = threadIdx.x >> 5;
    int lane = threadIdx.x & 31;
    if (b >= B) return;

    const float4* h4 = (const float4*)(g_h1 + b * H);
    const float4* c4 = (const float4*)(d_out_ctx + CTX_OFF + b * H);
    const float4* w4 = (const float4*)(w_concat + (long)j * 2 * H);

    float4 wv0[4], wv1[4], hv[4], cv[4];
#pragma unroll
    for (int i = 0; i < 4; i++) {
        int c = lane + 32 * i;
        wv0[i] = __ldg(&w4[c]);
        wv1[i] = __ldg(&w4[H / 4 + c]);
        hv[i]  = h4[c];
        cv[i]  = c4[c];
    }
    float s0 = 0.f, s1 = 0.f;
#pragma unroll
    for (int i = 0; i < 4; i++) {
        s0 += dot4(hv[i], wv0[i]);
        s1 += dot4(cv[i], wv1[i]);
    }
    float s = warp_sum(s0 + s1);
    if (lane == 0) g_concat[b * H + j] = tanhf(s + b_concat[j]);
}

// ---------------------------------------------------------------------------
// Kernel 5: output = concat @ w_out.T + b_out. (10 x 512 x 32000 fp32 GEMM)
// 1000 blocks x 256 thr. Packed fma.rn.f32x2 over k-pairs: float4 loads
// reinterpret as ulonglong2 (consecutive regs) -> zero-cost packing, halving
// the FMA instruction count (640 FFMA -> 320 f32x2 per thread).
// ---------------------------------------------------------------------------
__global__ void __launch_bounds__(256)
out_kernel(const float* __restrict__ w_out,
           const float* __restrict__ b_out,
           float* __restrict__ d_out) {
    __shared__ float cs[B * H];  // 20 KB
    for (int i = threadIdx.x; i < B * H; i += 256) cs[i] = g_concat[i];
    __syncthreads();

    int warp = threadIdx.x >> 5;
    int lane = threadIdx.x & 31;
    int v0 = blockIdx.x * 32 + warp * 4;

    float bias[4];
#pragma unroll
    for (int i = 0; i < 4; i++) bias[i] = __ldg(&b_out[v0 + i]);

    const float4* w0 = (const float4*)(w_out + (long)v0 * H);
    const float4* cs4 = (const float4*)cs;

    // packed accumulators: even/odd-k partial sums per (row, batch)
    unsigned long long acc2[4][B];
#pragma unroll
    for (int i = 0; i < 4; i++)
#pragma unroll
        for (int bb = 0; bb < B; bb++) acc2[i][bb] = 0ULL;

#pragma unroll
    for (int c = 0; c < 4; c++) {
        int k4 = c * 32 + lane;
        // per-chunk weight quads (keeps regs ~120 -> 2 blocks/SM)
        float4 wq[4];
#pragma unroll
        for (int i = 0; i < 4; i++) wq[i] = __ldg(&w0[i * (H / 4) + k4]);

#pragma unroll
        for (int bb = 0; bb < B; bb++) {
            float4 cq = cs4[bb * (H / 4) + k4];
            ulonglong2 cp = *reinterpret_cast<ulonglong2*>(&cq);
#pragma unroll
            for (int i = 0; i < 4; i++) {
                ulonglong2 wp = *reinterpret_cast<ulonglong2*>(&wq[i]);
                asm("fma.rn.f32x2 %0, %1, %2, %0;"
                    : "+l"(acc2[i][bb]) : "l"(wp.x), "l"(cp.x));
                asm("fma.rn.f32x2 %0, %1, %2, %0;"
                    : "+l"(acc2[i][bb]) : "l"(wp.y), "l"(cp.y));
            }
        }
    }

#pragma unroll
    for (int i = 0; i < 4; i++) {
#pragma unroll
        for (int bb = 0; bb < B; bb++) {
            unsigned long long a = acc2[i][bb];
            float lo = __uint_as_float((unsigned)(a & 0xffffffffULL));
            float hi = __uint_as_float((unsigned)(a >> 32));
            float s = warp_sum(lo + hi);
            if (lane == 0)
                d_out[OUT_OFF + (long)bb * VOCAB + v0 + i] = s + bias[i];
        }
    }
}

// ---------------------------------------------------------------------------
extern "C" void kernel_launch(void* const* d_in, const int* in_sizes, int n_in,
                              void* d_out, int out_size) {
    const int*   input_seq  = (const int*)d_in[0];
    const int*   kb_inputs  = (const int*)d_in[1];
    // d_in[2] = last_context (unused by the reference math)
    const float* last_hidden = (const float*)d_in[3];
    const float* enc        = (const float*)d_in[4];
    const float* emb        = (const float*)d_in[5];
    const float* emb_kb     = (const float*)d_in[6];
    const float* w_ih       = (const float*)d_in[7];
    const float* w_hh       = (const float*)d_in[8];
    const float* b_ih       = (const float*)d_in[9];
    const float* b_hh       = (const float*)d_in[10];
    const float* w_concat   = (const float*)d_in[11];
    const float* b_concat   = (const float*)d_in[12];
    const float* w_out      = (const float*)d_in[13];
    const float* b_out      = (const float*)d_in[14];
    float* out = (float*)d_out;

    // lazily created host-side resources (streams/events are not device mem)
    static cudaStream_t s_kb = nullptr;
    static cudaEvent_t  e_fork = nullptr, e_join = nullptr;
    if (s_kb == nullptr) {
        cudaStreamCreateWithFlags(&s_kb, cudaStreamNonBlocking);
        cudaEventCreateWithFlags(&e_fork, cudaEventDisableTiming);
        cudaEventCreateWithFlags(&e_join, cudaEventDisableTiming);
    }

    // fork: kb branch runs concurrently with the whole chain
    cudaEventRecord(e_fork, 0);
    cudaStreamWaitEvent(s_kb, e_fork, 0);
    kb_kernel<<<2048, 256, 0, s_kb>>>(kb_inputs, emb_kb, out);
    cudaEventRecord(e_join, s_kb);

    // dependency chain on the main stream
    gru_kernel<<<H, 320>>>(input_seq, emb, last_hidden,
                           w_ih, w_hh, b_ih, b_hh, out);
    attn_kernel<<<L, 320>>>(enc, out);
    ctx_kernel<<<B * 16, 512>>>(enc, out);
    concat_kernel<<<H, 320>>>(w_concat, b_concat, out);
    out_kernel<<<VOCAB / 32, 256>>>(w_out, b_out, out);

    // join: graph completes only when kb branch is done
    cudaStreamWaitEvent(0, e_join, 0);
}

// round 13
// speedup vs baseline: 1.1250x; 1.1250x over previous
#include <cuda_runtime.h>
#include <cuda_bf16.h>
#include <math.h>

#define VOCAB 32000
#define H 512
#define B 10
#define KB 431
#define KB_PAD 1523
#define KBW (KB_PAD + KB)      // 1954
#define L H                     // 512

// d_out layout (floats), concatenation of the 5 reference outputs:
#define OUT_OFF   0
#define CTX_OFF   (VOCAB * B)                 // 320000
#define HID_OFF   (CTX_OFF + B * H)           // 325120
#define ATTN_OFF  (HID_OFF + B * H)           // 330240
#define KBA_OFF   (ATTN_OFF + B * L)          // 335360
#define KBA_TOT   (B * L * KBW)               // 10004480
#define N4        (KBA_TOT / 4)               // 2501120

// scratch (no device allocation allowed)
__device__ float g_h1[B * H];
__device__ float g_concat[B * H];

__device__ __forceinline__ float dot4(float4 a, float4 b) {
    return a.x * b.x + a.y * b.y + a.z * b.z + a.w * b.w;
}

__device__ __forceinline__ float warp_sum(float v) {
#pragma unroll
    for (int o = 16; o > 0; o >>= 1) v += __shfl_xor_sync(0xFFFFFFFFu, v, o);
    return v;
}

__device__ __forceinline__ float sigmoidf_(float x) {
    return 1.0f / (1.0f + __expf(-x));
}

// ---------------------------------------------------------------------------
// kb kernel (side stream): grid-stride over output float4 quads.
// Fast path: quad inside one (b,p) row; slow path handles row straddle.
// ---------------------------------------------------------------------------
__global__ void __launch_bounds__(256)
kb_kernel(const int* __restrict__ kb_inputs,
          const float* __restrict__ emb_kb,
          float* __restrict__ d_out) {
    const unsigned ROW = (unsigned)L * KBW;   // 1000448
    unsigned stride = gridDim.x * blockDim.x;
    for (unsigned i4 = blockIdx.x * blockDim.x + threadIdx.x; i4 < (unsigned)N4;
         i4 += stride) {
        unsigned t   = i4 * 4u;
        unsigned b   = t / ROW;
        unsigned rem = t - b * ROW;
        unsigned p   = rem / KBW;
        unsigned c   = rem - p * KBW;
        float v[4] = {0.f, 0.f, 0.f, 0.f};

        if (c + 3u < (unsigned)KBW) {
            if (c + 3u >= (unsigned)KB_PAD) {
#pragma unroll
                for (int j = 0; j < 4; j++) {
                    unsigned cj = c + j;
                    if (cj >= (unsigned)KB_PAD) {
                        unsigned f = p * KB + (cj - KB_PAD);
                        unsigned kbr = f >> 9, h = f & 511u;
                        const int* idx = kb_inputs + ((long)b * KB + kbr) * 3;
                        v[j] = __ldg(&emb_kb[(long)__ldg(idx + 0) * H + h])
                             + __ldg(&emb_kb[(long)__ldg(idx + 1) * H + h])
                             + __ldg(&emb_kb[(long)__ldg(idx + 2) * H + h]);
                    }
                }
            }
        } else {
#pragma unroll
            for (int j = 0; j < 4; j++) {
                unsigned tj = t + j;
                unsigned bj = tj / ROW;
                unsigned rj = tj - bj * ROW;
                unsigned pj = rj / KBW;
                unsigned cj = rj - pj * KBW;
                if (cj >= (unsigned)KB_PAD) {
                    unsigned f = pj * KB + (cj - KB_PAD);
                    unsigned kbr = f >> 9, h = f & 511u;
                    const int* idx = kb_inputs + ((long)bj * KB + kbr) * 3;
                    v[j] = __ldg(&emb_kb[(long)__ldg(idx + 0) * H + h])
                         + __ldg(&emb_kb[(long)__ldg(idx + 1) * H + h])
                         + __ldg(&emb_kb[(long)__ldg(idx + 2) * H + h]);
                }
            }
        }
        float4 o;
        o.x = v[0]; o.y = v[1]; o.z = v[2]; o.w = v[3];
        ((float4*)(d_out + KBA_OFF))[i4] = o;
    }
}

// ---------------------------------------------------------------------------
// Kernel 1: GRU step. grid = H blocks, 320 threads (warp = batch b).
// Also writes hidden output and zeros context slab.
// ---------------------------------------------------------------------------
__global__ void __launch_bounds__(320)
gru_kernel(const int* __restrict__ seq,
           const float* __restrict__ emb,
           const float* __restrict__ h0,
           const float* __restrict__ w_ih,
           const float* __restrict__ w_hh,
           const float* __restrict__ b_ih,
           const float* __restrict__ b_hh,
           float* __restrict__ d_out) {
    int j = blockIdx.x;
    int b = threadIdx.x >> 5;
    int lane = threadIdx.x & 31;
    if (b >= B) return;

    const float4* x4  = (const float4*)(emb + (long)seq[b] * H);
    const float4* h4  = (const float4*)(h0 + b * H);
    const float4* wir = (const float4*)(w_ih + (long)j * H);
    const float4* wiz = (const float4*)(w_ih + (long)(H + j) * H);
    const float4* win = (const float4*)(w_ih + (long)(2 * H + j) * H);
    const float4* whr = (const float4*)(w_hh + (long)j * H);
    const float4* whz = (const float4*)(w_hh + (long)(H + j) * H);
    const float4* whn = (const float4*)(w_hh + (long)(2 * H + j) * H);

    float sir = 0.f, siz = 0.f, sin_ = 0.f, shr = 0.f, shz = 0.f, shn = 0.f;
#pragma unroll
    for (int c = lane; c < H / 4; c += 32) {
        float4 xv = x4[c], hv = h4[c];
        sir  += dot4(xv, wir[c]);
        siz  += dot4(xv, wiz[c]);
        sin_ += dot4(xv, win[c]);
        shr  += dot4(hv, whr[c]);
        shz  += dot4(hv, whz[c]);
        shn  += dot4(hv, whn[c]);
    }
    sir = warp_sum(sir);  siz = warp_sum(siz);  sin_ = warp_sum(sin_);
    shr = warp_sum(shr);  shz = warp_sum(shz);  shn  = warp_sum(shn);

    if (lane == 0) {
        float gir = sir + b_ih[j];
        float giz = siz + b_ih[H + j];
        float gin = sin_ + b_ih[2 * H + j];
        float ghr = shr + b_hh[j];
        float ghz = shz + b_hh[H + j];
        float ghn = shn + b_hh[2 * H + j];
        float r = sigmoidf_(gir + ghr);
        float z = sigmoidf_(giz + ghz);
        float n = tanhf(gin + r * ghn);
        float hprev = h0[b * H + j];
        float h1 = (1.0f - z) * n + z * hprev;
        g_h1[b * H + j] = h1;
        d_out[HID_OFF + b * H + j] = h1;
        d_out[CTX_OFF + b * H + j] = 0.0f;  // zero context for atomicAdd
    }
}

// ---------------------------------------------------------------------------
// Kernel 2: energies + softmax over batch (axis 0). grid = L blocks, 320 thr.
// ---------------------------------------------------------------------------
__global__ void __launch_bounds__(320)
attn_kernel(const float* __restrict__ enc,
            float* __restrict__ d_out) {
    int l = blockIdx.x;
    int b = threadIdx.x >> 5;
    int lane = threadIdx.x & 31;
    __shared__ float e_s[B];

    if (b < B) {
        const float4* h4 = (const float4*)(g_h1 + b * H);
        const float4* e4 = (const float4*)(enc + ((long)l * B + b) * H);
        float s = 0.f;
#pragma unroll
        for (int c = lane; c < H / 4; c += 32) s += dot4(h4[c], e4[c]);
        s = warp_sum(s);
        if (lane == 0) e_s[b] = s;
    }
    __syncthreads();
    if (threadIdx.x < B) {
        float m = -1e30f;
#pragma unroll
        for (int i = 0; i < B; i++) m = fmaxf(m, e_s[i]);
        float sum = 0.f;
#pragma unroll
        for (int i = 0; i < B; i++) sum += __expf(e_s[i] - m);
        float a = __expf(e_s[threadIdx.x] - m) / sum;
        d_out[ATTN_OFF + threadIdx.x * L + l] = a;
    }
}

// ---------------------------------------------------------------------------
// Kernel 3: context[b,h] = sum_l a[b,l]*enc[l,b,h]. 320 blocks (b, l-chunk
// of 16) x 512 thr — doubled grid vs R9 (occ was pinned at 26%, ~1 block/SM;
// more resident warps -> more loads in flight under kb-stream contention).
// Explicit 8-wide load batches keep LDGs front-batched. Atomic depth 32.
// ---------------------------------------------------------------------------
__global__ void __launch_bounds__(512)
ctx_kernel(const float* __restrict__ enc,
           float* __restrict__ d_out) {
    __shared__ float a_s[16];
    int b  = blockIdx.x >> 5;
    int lc = blockIdx.x & 31;
    int h  = threadIdx.x;

    if (threadIdx.x < 16)
        a_s[threadIdx.x] = d_out[ATTN_OFF + b * L + lc * 16 + threadIdx.x];
    __syncthreads();

    const float* ep = enc + ((long)(lc * 16) * B + b) * H + h;
    float acc = 0.f;
#pragma unroll
    for (int base = 0; base < 16; base += 8) {
        float r[8];
#pragma unroll
        for (int j = 0; j < 8; j++) r[j] = __ldg(ep + (long)(base + j) * B * H);
#pragma unroll
        for (int j = 0; j < 8; j++) acc = fmaf(a_s[base + j], r[j], acc);
    }
    atomicAdd(&d_out[CTX_OFF + b * H + h], acc);
}

// ---------------------------------------------------------------------------
// Kernel 4: concat_output = tanh([h1, ctx] @ w_concat.T + b_concat).
// grid = H blocks, warp per batch. All 16 load quads front-batched.
// ---------------------------------------------------------------------------
__global__ void __launch_bounds__(320)
concat_kernel(const float* __restrict__ w_concat,
              const float* __restrict__ b_concat,
              const float* __restrict__ d_out_ctx) {
    int j = blockIdx.x;
    int b = threadIdx.x >> 5;
    int lane = threadIdx.x & 31;
    if (b >= B) return;

    const float4* h4 = (const float4*)(g_h1 + b * H);
    const float4* c4 = (const float4*)(d_out_ctx + CTX_OFF + b * H);
    const float4* w4 = (const float4*)(w_concat + (long)j * 2 * H);

    float4 wv0[4], wv1[4], hv[4], cv[4];
#pragma unroll
    for (int i = 0; i < 4; i++) {
        int c = lane + 32 * i;
        wv0[i] = __ldg(&w4[c]);
        wv1[i] = __ldg(&w4[H / 4 + c]);
        hv[i]  = h4[c];
        cv[i]  = c4[c];
    }
    float s0 = 0.f, s1 = 0.f;
#pragma unroll
    for (int i = 0; i < 4; i++) {
        s0 += dot4(hv[i], wv0[i]);
        s1 += dot4(cv[i], wv1[i]);
    }
    float s = warp_sum(s0 + s1);
    if (lane == 0) g_concat[b * H + j] = tanhf(s + b_concat[j]);
}

// ---------------------------------------------------------------------------
// Kernel 5: output = concat @ w_out.T + b_out. (10 x 512 x 32000 fp32 GEMM)
// 1000 blocks x 256 thr. R9 scalar form (f32x2 variant regressed in R12).
// ---------------------------------------------------------------------------
__global__ void __launch_bounds__(256)
out_kernel(const float* __restrict__ w_out,
           const float* __restrict__ b_out,
           float* __restrict__ d_out) {
    __shared__ float cs[B * H];  // 20 KB
    for (int i = threadIdx.x; i < B * H; i += 256) cs[i] = g_concat[i];
    __syncthreads();

    int warp = threadIdx.x >> 5;
    int lane = threadIdx.x & 31;
    int v0 = blockIdx.x * 32 + warp * 4;

    float bias[4];
#pragma unroll
    for (int i = 0; i < 4; i++) bias[i] = __ldg(&b_out[v0 + i]);

    const float4* w0 = (const float4*)(w_out + (long)v0 * H);
    const float4* cs4 = (const float4*)cs;

    // front-batch all 16 weight quads (4 k-chunks x 4 vocab rows)
    float4 wv[4][4];
#pragma unroll
    for (int c = 0; c < 4; c++) {
        int k4 = c * 32 + lane;
#pragma unroll
        for (int i = 0; i < 4; i++) wv[c][i] = __ldg(&w0[i * (H / 4) + k4]);
    }

    float acc[4][B];
#pragma unroll
    for (int i = 0; i < 4; i++)
#pragma unroll
        for (int bb = 0; bb < B; bb++) acc[i][bb] = 0.f;

#pragma unroll
    for (int c = 0; c < 4; c++) {
        int k4 = c * 32 + lane;
#pragma unroll
        for (int bb = 0; bb < B; bb++) {
            float4 cv = cs4[bb * (H / 4) + k4];
#pragma unroll
            for (int i = 0; i < 4; i++) {
                acc[i][bb] += wv[c][i].x * cv.x + wv[c][i].y * cv.y
                            + wv[c][i].z * cv.z + wv[c][i].w * cv.w;
            }
        }
    }

#pragma unroll
    for (int i = 0; i < 4; i++) {
#pragma unroll
        for (int bb = 0; bb < B; bb++) {
            float s = warp_sum(acc[i][bb]);
            if (lane == 0)
                d_out[OUT_OFF + (long)bb * VOCAB + v0 + i] = s + bias[i];
        }
    }
}

// ---------------------------------------------------------------------------
extern "C" void kernel_launch(void* const* d_in, const int* in_sizes, int n_in,
                              void* d_out, int out_size) {
    const int*   input_seq  = (const int*)d_in[0];
    const int*   kb_inputs  = (const int*)d_in[1];
    // d_in[2] = last_context (unused by the reference math)
    const float* last_hidden = (const float*)d_in[3];
    const float* enc        = (const float*)d_in[4];
    const float* emb        = (const float*)d_in[5];
    const float* emb_kb     = (const float*)d_in[6];
    const float* w_ih       = (const float*)d_in[7];
    const float* w_hh       = (const float*)d_in[8];
    const float* b_ih       = (const float*)d_in[9];
    const float* b_hh       = (const float*)d_in[10];
    const float* w_concat   = (const float*)d_in[11];
    const float* b_concat   = (const float*)d_in[12];
    const float* w_out      = (const float*)d_in[13];
    const float* b_out      = (const float*)d_in[14];
    float* out = (float*)d_out;

    // lazily created host-side resources (streams/events are not device mem)
    static cudaStream_t s_kb = nullptr;
    static cudaEvent_t  e_fork = nullptr, e_join = nullptr;
    if (s_kb == nullptr) {
        cudaStreamCreateWithFlags(&s_kb, cudaStreamNonBlocking);
        cudaEventCreateWithFlags(&e_fork, cudaEventDisableTiming);
        cudaEventCreateWithFlags(&e_join, cudaEventDisableTiming);
    }

    // fork: kb branch runs concurrently with the whole chain
    cudaEventRecord(e_fork, 0);
    cudaStreamWaitEvent(s_kb, e_fork, 0);
    kb_kernel<<<2048, 256, 0, s_kb>>>(kb_inputs, emb_kb, out);
    cudaEventRecord(e_join, s_kb);

    // dependency chain on the main stream
    gru_kernel<<<H, 320>>>(input_seq, emb, last_hidden,
                           w_ih, w_hh, b_ih, b_hh, out);
    attn_kernel<<<L, 320>>>(enc, out);
    ctx_kernel<<<B * 32, 512>>>(enc, out);
    concat_kernel<<<H, 320>>>(w_concat, b_concat, out);
    out_kernel<<<VOCAB / 32, 256>>>(w_out, b_out, out);

    // join: graph completes only when kb branch is done
    cudaStreamWaitEvent(0, e_join, 0);
}